// round 5
// baseline (speedup 1.0000x reference)
#include <cuda_runtime.h>
#include <math.h>

#define D_DIM   64
#define SPLIT   128          // collect units per batch (64 rows each)
#define MAXB    64
#define UNITS   (MAXB * SPLIT)   // 8192 units for both kernels
#define GRID_P  1184             // 8 CTAs/SM * 148 SMs; extras exit free

// Scratch (no device allocs allowed)
__device__ float g_part_m[MAXB * SPLIT];
__device__ float g_part_s[MAXB * SPLIT];
__device__ float g_part_acc[MAXB * SPLIT * D_DIM];
__device__ float g_attn[MAXB * D_DIM];
__device__ unsigned int g_ctr_a;
__device__ unsigned int g_ctr_c;

__global__ void reset_kernel() { g_ctr_a = 0; g_ctr_c = 0; }

// ---------------------------------------------------------------------------
// Kernel A: persistent work-stealing collect. Unit = (b, sp) -> 64 rows.
// 256 threads = 8 warps; warp does 4 rows/iter (2 iters/unit).
// Lane owns elements [2*lane, 2*lane+1] of the D=64 vectors.
// ---------------------------------------------------------------------------
__global__ __launch_bounds__(256) void collect_kernel(
    const float* __restrict__ q, const float* __restrict__ kc,
    const float* __restrict__ v, const float* __restrict__ tcp,
    float* __restrict__ logits, int L)
{
    const int warp = threadIdx.x >> 5;
    const int lane = threadIdx.x & 31;
    const int rows = L / SPLIT;           // 64
    const float inv_tc = __frcp_rn(tcp[0]);

    __shared__ unsigned s_next;
    __shared__ float sm_m[8];
    __shared__ float sm_s[8];
    __shared__ float sm_acc[8][D_DIM];

    if (threadIdx.x == 0) s_next = atomicAdd(&g_ctr_a, 1u);
    __syncthreads();

    for (;;) {
        const unsigned unit = s_next;
        __syncthreads();                  // everyone has `unit`; prev epilogue reads done
        if (unit >= UNITS) break;
        if (threadIdx.x == 0) s_next = atomicAdd(&g_ctr_a, 1u);  // prefetch next unit

        const int b  = unit >> 7;         // / SPLIT
        const int sp = unit & (SPLIT - 1);
        const int l0 = sp * rows;

        const float2 q2 = ((const float2*)(q + b * D_DIM))[lane];
        const float* kcb = kc + ((size_t)b * L + l0) * D_DIM;
        const float* vb  = v  + ((size_t)b * L + l0) * D_DIM;
        float*       lgb = logits + (size_t)b * L + l0;

        float m = -1e30f, s = 0.0f, accx = 0.0f, accy = 0.0f;

        #pragma unroll
        for (int i0 = warp * 4; i0 < rows; i0 += 32) {
            float2 k0 = *(const float2*)(kcb + (i0 + 0) * D_DIM + 2 * lane);
            float2 k1 = *(const float2*)(kcb + (i0 + 1) * D_DIM + 2 * lane);
            float2 k2 = *(const float2*)(kcb + (i0 + 2) * D_DIM + 2 * lane);
            float2 k3 = *(const float2*)(kcb + (i0 + 3) * D_DIM + 2 * lane);
            float2 v0 = *(const float2*)(vb  + (i0 + 0) * D_DIM + 2 * lane);
            float2 v1 = *(const float2*)(vb  + (i0 + 1) * D_DIM + 2 * lane);
            float2 v2 = *(const float2*)(vb  + (i0 + 2) * D_DIM + 2 * lane);
            float2 v3 = *(const float2*)(vb  + (i0 + 3) * D_DIM + 2 * lane);

            float d0 = k0.x * q2.x + k0.y * q2.y;
            float d1 = k1.x * q2.x + k1.y * q2.y;
            float d2 = k2.x * q2.x + k2.y * q2.y;
            float d3 = k3.x * q2.x + k3.y * q2.y;

            #pragma unroll
            for (int off = 16; off; off >>= 1) {
                d0 += __shfl_xor_sync(0xffffffffu, d0, off);
                d1 += __shfl_xor_sync(0xffffffffu, d1, off);
                d2 += __shfl_xor_sync(0xffffffffu, d2, off);
                d3 += __shfl_xor_sync(0xffffffffu, d3, off);
            }
            d0 *= inv_tc; d1 *= inv_tc; d2 *= inv_tc; d3 *= inv_tc;

            if (lane == 0)
                *(float4*)(lgb + i0) = make_float4(d0, d1, d2, d3);

            float mx    = fmaxf(fmaxf(d0, d1), fmaxf(d2, d3));
            float m_new = fmaxf(m, mx);
            float c  = __expf(m - m_new);
            float p0 = __expf(d0 - m_new);
            float p1 = __expf(d1 - m_new);
            float p2 = __expf(d2 - m_new);
            float p3 = __expf(d3 - m_new);
            s    = s * c + (p0 + p1) + (p2 + p3);
            accx = accx * c + p0 * v0.x + p1 * v1.x + p2 * v2.x + p3 * v3.x;
            accy = accy * c + p0 * v0.y + p1 * v1.y + p2 * v2.y + p3 * v3.y;
            m = m_new;
        }

        sm_acc[warp][2 * lane]     = accx;
        sm_acc[warp][2 * lane + 1] = accy;
        if (lane == 0) { sm_m[warp] = m; sm_s[warp] = s; }
        __syncthreads();

        const int t = threadIdx.x;
        if (t < D_DIM) {
            float M = sm_m[0];
            #pragma unroll
            for (int w = 1; w < 8; w++) M = fmaxf(M, sm_m[w]);
            float S = 0.0f, A = 0.0f;
            #pragma unroll
            for (int w = 0; w < 8; w++) {
                float e = __expf(sm_m[w] - M);
                S += sm_s[w] * e;
                A += sm_acc[w][t] * e;
            }
            g_part_acc[unit * D_DIM + t] = A;
            if (t == 0) { g_part_m[unit] = M; g_part_s[unit] = S; }
        }
        // loop-top __syncthreads separates these smem reads from next unit's writes
    }
}

// ---------------------------------------------------------------------------
// Kernel B: merge the SPLIT partials per batch -> normalized attn[b][64].
// ---------------------------------------------------------------------------
__global__ __launch_bounds__(64) void reduce_kernel()
{
    int b = blockIdx.x;
    int d = threadIdx.x;  // 64 threads
    float M = -1e30f;
    #pragma unroll 8
    for (int j = 0; j < SPLIT; j++)
        M = fmaxf(M, g_part_m[b * SPLIT + j]);
    float S = 0.0f, A = 0.0f;
    #pragma unroll 8
    for (int j = 0; j < SPLIT; j++) {
        float e = __expf(g_part_m[b * SPLIT + j] - M);
        S += g_part_s[b * SPLIT + j] * e;
        A += g_part_acc[(b * SPLIT + j) * D_DIM + d] * e;
    }
    g_attn[b * D_DIM + d] = A / S;
}

// ---------------------------------------------------------------------------
// Kernel C: persistent work-stealing diffuse. Unit = 64 rows.
// gate = sigmoid(dot(kd,q)/td); out = gate * attn[b].
// ---------------------------------------------------------------------------
__global__ __launch_bounds__(256) void diffuse_kernel(
    const float* __restrict__ q, const float* __restrict__ kd,
    const float* __restrict__ tdp, float* __restrict__ out, int L)
{
    const int warp = threadIdx.x >> 5;
    const int lane = threadIdx.x & 31;
    const int tiles_per_b = L / 64;       // 128
    const float inv_td = __frcp_rn(tdp[0]);

    __shared__ unsigned s_next;

    if (threadIdx.x == 0) s_next = atomicAdd(&g_ctr_c, 1u);
    __syncthreads();

    for (;;) {
        const unsigned unit = s_next;
        __syncthreads();
        if (unit >= UNITS) break;
        if (threadIdx.x == 0) s_next = atomicAdd(&g_ctr_c, 1u);

        const int b  = unit / tiles_per_b;
        const int l0 = (unit % tiles_per_b) * 64;

        const float2 q2 = ((const float2*)(q + b * D_DIM))[lane];
        const float2 a2 = ((const float2*)(g_attn + b * D_DIM))[lane];
        const float* kdb = kd  + ((size_t)b * L + l0) * D_DIM;
        float*       ob  = out + ((size_t)b * L + l0) * D_DIM;

        #pragma unroll
        for (int i0 = warp * 4; i0 < 64; i0 += 32) {
            float2 k0 = *(const float2*)(kdb + (i0 + 0) * D_DIM + 2 * lane);
            float2 k1 = *(const float2*)(kdb + (i0 + 1) * D_DIM + 2 * lane);
            float2 k2 = *(const float2*)(kdb + (i0 + 2) * D_DIM + 2 * lane);
            float2 k3 = *(const float2*)(kdb + (i0 + 3) * D_DIM + 2 * lane);

            float d0 = k0.x * q2.x + k0.y * q2.y;
            float d1 = k1.x * q2.x + k1.y * q2.y;
            float d2 = k2.x * q2.x + k2.y * q2.y;
            float d3 = k3.x * q2.x + k3.y * q2.y;

            #pragma unroll
            for (int off = 16; off; off >>= 1) {
                d0 += __shfl_xor_sync(0xffffffffu, d0, off);
                d1 += __shfl_xor_sync(0xffffffffu, d1, off);
                d2 += __shfl_xor_sync(0xffffffffu, d2, off);
                d3 += __shfl_xor_sync(0xffffffffu, d3, off);
            }

            float g0 = __frcp_rn(1.0f + __expf(-d0 * inv_td));
            float g1 = __frcp_rn(1.0f + __expf(-d1 * inv_td));
            float g2 = __frcp_rn(1.0f + __expf(-d2 * inv_td));
            float g3 = __frcp_rn(1.0f + __expf(-d3 * inv_td));

            *(float2*)(ob + (i0 + 0) * D_DIM + 2 * lane) = make_float2(g0 * a2.x, g0 * a2.y);
            *(float2*)(ob + (i0 + 1) * D_DIM + 2 * lane) = make_float2(g1 * a2.x, g1 * a2.y);
            *(float2*)(ob + (i0 + 2) * D_DIM + 2 * lane) = make_float2(g2 * a2.x, g2 * a2.y);
            *(float2*)(ob + (i0 + 3) * D_DIM + 2 * lane) = make_float2(g3 * a2.x, g3 * a2.y);
        }
        __syncthreads();   // s_next write (this iter) ordered before next read
    }
}

// ---------------------------------------------------------------------------
// Launch: inputs in metadata order: q, kc, kd, v, tc, td.
// d_out layout (tuple order): output [B,L,D] then logits [B,L].
// ---------------------------------------------------------------------------
extern "C" void kernel_launch(void* const* d_in, const int* in_sizes, int n_in,
                              void* d_out, int out_size)
{
    const float* q  = (const float*)d_in[0];
    const float* kc = (const float*)d_in[1];
    const float* kd = (const float*)d_in[2];
    const float* v  = (const float*)d_in[3];
    const float* tc = (const float*)d_in[4];
    const float* td = (const float*)d_in[5];

    int B = in_sizes[0] / D_DIM;           // q is [B,1,D]
    int L = in_sizes[1] / (B * D_DIM);     // kc is [B,L,D]

    float* out    = (float*)d_out;
    float* logits = out + (size_t)B * L * D_DIM;

    reset_kernel<<<1, 1>>>();
    collect_kernel<<<GRID_P, 256>>>(q, kc, v, tc, logits, L);
    reduce_kernel<<<B, D_DIM>>>();
    diffuse_kernel<<<GRID_P, 256>>>(q, kd, td, out, L);
}